// round 16
// baseline (speedup 1.0000x reference)
#include <cuda_runtime.h>
#include <float.h>

// ROI max pooling, SINGLE kernel, single wave, clamp-based OOB.
// feat: [B=8, H=50, W=50, C=256] fp32 NHWC; rois: [N,5] (img,x1,y1,x2,y2) incl.
// Dataset ROIs are 28x28 with 7x7 pooling -> each bin = aligned 4x4 window at
// (y1+4br, x1+4bc). 4x4 tiles partition the 47x47 window-origin grid; each
// tile CTA scans the ROI list for consumer bins, streams 7 input rows (direct
// LDG, float2/thread, coordinates CLAMPED to the image instead of predicated:
// consumed window origins are always <= 46, and clamped pixels only pollute
// origins >= 47 which are never scattered), parks the 4x4 maxes in smem,
// scatters to out. Non-28x28 ROIs run a strided general path (dataset no-op).

#define FH 50
#define FW 50
#define CCH 256
#define PH 7
#define PW 7
#define NXC 12                   // tiles per row: ceil(47/4)
#define NYC 12
#define NTILES (8 * NYC * NXC)   // 1152
#define MAXM 256                 // match-list capacity per tile

__device__ __forceinline__ float2 fmax2(float2 a, float2 b) {
    float2 r;
    r.x = fmaxf(a.x, b.x);
    r.y = fmaxf(a.y, b.y);
    return r;
}

__global__ __launch_bounds__(128, 8)
void roi_pool_fused(const float* __restrict__ feat,
                    const int*   __restrict__ rois,
                    float*       __restrict__ out,
                    int n_rois)
{
    const int tid  = threadIdx.x;        // 0..127
    const int coff = tid * 2;            // 2 channels per thread

    __shared__ float2 s_vm[16][128];     // finished 4x4 window maxes, 16 KB
    __shared__ int    s_m[MAXM];         // packed matches: obin*16 | loc
    __shared__ int    s_cnt;

    const int id = blockIdx.x;           // ((b*NYC)+ty)*NXC + tx
    const int tx = id % NXC;
    const int t1 = id / NXC;
    const int ty = t1 % NYC;
    const int b  = t1 / NYC;
    const int x0 = tx * 4;
    const int y0 = ty * 4;

    if (tid == 0) s_cnt = 0;
    __syncthreads();                     // s_cnt=0 visible before atomics

    // ---- Scan ROIs for consumer bins of this tile ----
    for (int roi = tid; roi < n_rois; roi += 128) {
        const int* r = rois + roi * 5;
        const int img = r[0], x1 = r[1], y1 = r[2], x2 = r[3], y2 = r[4];
        if (img != b) continue;
        if (y2 - y1 != 27 || x2 - x1 != 27) continue;  // general path below
        const int dy = y0 - y1;
        const int dx = x0 - x1;
        if (dy < -3 || dy > 24 || dx < -3 || dx > 24) continue;
        const int br = (dy + 3) >> 2;      // unique bin row landing in tile
        const int bc = (dx + 3) >> 2;
        const int yloc = 4 * br - dy;      // 0..3
        const int xloc = 4 * bc - dx;      // 0..3
        const int obin = (roi * PH + br) * PW + bc;    // <= 12543
        const int slot = atomicAdd(&s_cnt, 1);
        if (slot < MAXM)
            s_m[slot] = (obin << 4) | (yloc << 2) | xloc;
    }

    // ---- Streaming 4x4 window max, clamp-based OOB (no predication) ----
    float2 acc[4][4];
    #pragma unroll
    for (int r = 0; r < 4; ++r)
        #pragma unroll
        for (int c = 0; c < 4; ++c)
            acc[r][c] = make_float2(-FLT_MAX, -FLT_MAX);

    // Clamped column element-offsets (32-bit).
    unsigned xoff[7];
    #pragma unroll
    for (int k = 0; k < 7; ++k)
        xoff[k] = (unsigned)(min(x0 + k, FW - 1) * CCH);

    const float* bbase = feat + (unsigned)((b * FH) * FW * CCH + coff);

    #pragma unroll
    for (int j = 0; j < 7; ++j) {
        const int y = min(y0 + j, FH - 1);
        const float* rowp = bbase + (unsigned)(y * FW * CCH);
        float2 v[7];
        #pragma unroll
        for (int k = 0; k < 7; ++k)
            v[k] = *reinterpret_cast<const float2*>(rowp + xoff[k]);

        const float2 m01 = fmax2(v[0], v[1]);
        const float2 m12 = fmax2(v[1], v[2]);
        const float2 m23 = fmax2(v[2], v[3]);
        const float2 m34 = fmax2(v[3], v[4]);
        const float2 m45 = fmax2(v[4], v[5]);
        const float2 m56 = fmax2(v[5], v[6]);
        float2 h[4];
        h[0] = fmax2(m01, m23);
        h[1] = fmax2(m12, m34);
        h[2] = fmax2(m23, m45);
        h[3] = fmax2(m34, m56);

        #pragma unroll
        for (int r = 0; r < 4; ++r)
            if (j >= r && j <= r + 3)
                #pragma unroll
                for (int c = 0; c < 4; ++c)
                    acc[r][c] = fmax2(acc[r][c], h[c]);
    }

    // Park finished tile in smem for dynamically-indexed scatter reads.
    #pragma unroll
    for (int r = 0; r < 4; ++r)
        #pragma unroll
        for (int c = 0; c < 4; ++c)
            s_vm[r * 4 + c][tid] = acc[r][c];

    __syncthreads();   // park + match list visible

    // ---- Scatter: every thread writes its 2 channels per match ----
    const int cnt = min(s_cnt, MAXM);
    for (int i = 0; i < cnt; ++i) {
        const int m    = s_m[i];
        const int loc  = m & 15;             // yloc*4 + xloc
        const unsigned obin = (unsigned)(m >> 4);
        *reinterpret_cast<float2*>(
            out + (obin * (unsigned)CCH + (unsigned)coff))
            = s_vm[loc][tid];
    }

    // ---- General path for non-28x28 ROIs (CTA-uniform; dataset no-op) ----
    for (int roi = blockIdx.x; roi < n_rois; roi += NTILES) {
        const int* r = rois + roi * 5;
        const int img = r[0], x1 = r[1], y1 = r[2], x2 = r[3], y2 = r[4];
        const int roi_h = y2 - y1 + 1;
        const int roi_w = x2 - x1 + 1;
        if (roi_h == 28 && roi_w == 28) continue;   // handled above

        const float* base = feat
            + (((size_t)img * FH + (size_t)y1) * FW + (size_t)x1) * CCH + coff;
        for (int br = 0; br < PH; ++br) {
            const int rs = (br * roi_h + PH - 1) / PH;
            const int re = (br == PH - 1) ? roi_h
                                          : ((br + 1) * roi_h + PH - 1) / PH;
            for (int bc = 0; bc < PW; ++bc) {
                const int cs = (bc * roi_w + PW - 1) / PW;
                const int ce = (bc == PW - 1) ? roi_w
                                              : ((bc + 1) * roi_w + PW - 1) / PW;
                float2 m = make_float2(-FLT_MAX, -FLT_MAX);
                for (int y = rs; y < re; ++y) {
                    const float* rowp = base + (size_t)y * (FW * CCH);
                    for (int x = cs; x < ce; ++x) {
                        const float2 v =
                            *reinterpret_cast<const float2*>(rowp + (size_t)x * CCH);
                        m = fmax2(m, v);
                    }
                }
                *reinterpret_cast<float2*>(
                    out + ((size_t)((roi * PH + br) * PW + bc)) * CCH + coff) = m;
            }
        }
    }
}

extern "C" void kernel_launch(void* const* d_in, const int* in_sizes, int n_in,
                              void* d_out, int out_size)
{
    const float* feat = (const float*)d_in[0];
    const int*   rois = (const int*)d_in[1];
    const int n_rois = in_sizes[1] / 5;
    float* out = (float*)d_out;

    roi_pool_fused<<<NTILES, 128>>>(feat, rois, out, n_rois);
}

// round 17
// speedup vs baseline: 1.2186x; 1.2186x over previous
#include <cuda_runtime.h>
#include <float.h>

// ROI max pooling, SINGLE kernel, single wave (1152 CTAs = 8/SM).
// feat: [B=8, H=50, W=50, C=256] fp32 NHWC; rois: [N,5] (img,x1,y1,x2,y2) incl.
// Dataset ROIs are 28x28 with 7x7 pooling -> each bin = aligned 4x4 window at
// (y1+4br, x1+4bc). 4x4 tiles partition the 47x47 window-origin grid; each
// tile CTA scans the ROI list for consumer bins, streams 7 input rows (direct
// LDG, float2/thread), keeps the 4x4 window maxes in registers, parks them in
// smem, scatters to out with streaming stores. Non-28x28 ROIs are handled by
// the same CTAs via a strided general path (CTA-uniform, dataset no-op).

#define FH 50
#define FW 50
#define CCH 256
#define PH 7
#define PW 7
#define NXC 12                   // tiles per row: ceil(47/4)
#define NYC 12
#define NTILES (8 * NYC * NXC)   // 1152
#define MAXM 256                 // match-list capacity per tile

__device__ __forceinline__ float2 fmax2(float2 a, float2 b) {
    float2 r;
    r.x = fmaxf(a.x, b.x);
    r.y = fmaxf(a.y, b.y);
    return r;
}

__global__ __launch_bounds__(128, 8)
void roi_pool_fused(const float* __restrict__ feat,
                    const int*   __restrict__ rois,
                    float*       __restrict__ out,
                    int n_rois)
{
    const int tid  = threadIdx.x;        // 0..127
    const int coff = tid * 2;            // 2 channels per thread

    __shared__ float2 s_vm[16][128];     // finished 4x4 window maxes, 16 KB
    __shared__ int    s_m[MAXM];         // packed matches: obin<<4 | loc
    __shared__ int    s_cnt;

    const int id = blockIdx.x;           // ((b*NYC)+ty)*NXC + tx
    const int tx = id % NXC;
    const int t1 = id / NXC;
    const int ty = t1 % NYC;
    const int b  = t1 / NYC;
    const int x0 = tx * 4;
    const int y0 = ty * 4;

    if (tid == 0) s_cnt = 0;
    __syncthreads();                     // s_cnt=0 visible before atomics

    // ---- Scan ROIs first (overlaps with subsequent load issue) ----
    for (int roi = tid; roi < n_rois; roi += 128) {
        const int* r = rois + roi * 5;
        const int img = r[0], x1 = r[1], y1 = r[2], x2 = r[3], y2 = r[4];
        if (img != b) continue;
        if (y2 - y1 != 27 || x2 - x1 != 27) continue;  // general path below
        const int dy = y0 - y1;
        const int dx = x0 - x1;
        if (dy < -3 || dy > 24 || dx < -3 || dx > 24) continue;
        const int br = (dy + 3) >> 2;      // unique bin row landing in tile
        const int bc = (dx + 3) >> 2;
        const int yloc = 4 * br - dy;      // 0..3
        const int xloc = 4 * bc - dx;      // 0..3
        const int obin = (roi * PH + br) * PW + bc;
        const int slot = atomicAdd(&s_cnt, 1);
        if (slot < MAXM)
            s_m[slot] = (obin << 4) | (yloc << 2) | xloc;
    }

    // ---- Streaming 4x4 window max (32-bit addressing in hot path) ----
    const float2 NEG = make_float2(-FLT_MAX, -FLT_MAX);
    float2 acc[4][4];
    #pragma unroll
    for (int r = 0; r < 4; ++r)
        #pragma unroll
        for (int c = 0; c < 4; ++c)
            acc[r][c] = NEG;

    // base for (b, y0, x0, coff); all element offsets < 2^31
    const float* tbase = feat
        + (unsigned)(((b * FH + y0) * FW + x0) * CCH + coff);

    #pragma unroll
    for (int j = 0; j < 7; ++j) {
        const int y = y0 + j;
        float2 v[7];
        if (y < FH) {
            const float* rowp = tbase + (unsigned)(j * FW * CCH);
            #pragma unroll
            for (int k = 0; k < 7; ++k) {
                v[k] = (x0 + k < FW)
                     ? *reinterpret_cast<const float2*>(rowp + (unsigned)(k * CCH))
                     : NEG;
            }
        } else {
            #pragma unroll
            for (int k = 0; k < 7; ++k) v[k] = NEG;
        }
        const float2 m01 = fmax2(v[0], v[1]);
        const float2 m12 = fmax2(v[1], v[2]);
        const float2 m23 = fmax2(v[2], v[3]);
        const float2 m34 = fmax2(v[3], v[4]);
        const float2 m45 = fmax2(v[4], v[5]);
        const float2 m56 = fmax2(v[5], v[6]);
        float2 h[4];
        h[0] = fmax2(m01, m23);
        h[1] = fmax2(m12, m34);
        h[2] = fmax2(m23, m45);
        h[3] = fmax2(m34, m56);

        #pragma unroll
        for (int r = 0; r < 4; ++r)
            if (j >= r && j <= r + 3)
                #pragma unroll
                for (int c = 0; c < 4; ++c)
                    acc[r][c] = fmax2(acc[r][c], h[c]);
    }

    // Park finished tile in smem for dynamically-indexed scatter reads.
    #pragma unroll
    for (int r = 0; r < 4; ++r)
        #pragma unroll
        for (int c = 0; c < 4; ++c)
            s_vm[r * 4 + c][tid] = acc[r][c];

    __syncthreads();   // park + match list visible

    // ---- Scatter: streaming stores (out is write-once, keep L2 for feat) --
    const int cnt = min(s_cnt, MAXM);
    for (int i = 0; i < cnt; ++i) {
        const int m   = s_m[i];
        const int loc = m & 15;            // yloc*4 + xloc
        const unsigned obin = (unsigned)(m >> 4);
        __stwt(reinterpret_cast<float2*>(
                   out + (obin * (unsigned)CCH + (unsigned)coff)),
               s_vm[loc][tid]);
    }

    // ---- General path for non-28x28 ROIs (CTA-uniform; dataset no-op) ----
    for (int roi = blockIdx.x; roi < n_rois; roi += NTILES) {
        const int* r = rois + roi * 5;
        const int img = r[0], x1 = r[1], y1 = r[2], x2 = r[3], y2 = r[4];
        const int roi_h = y2 - y1 + 1;
        const int roi_w = x2 - x1 + 1;
        if (roi_h == 28 && roi_w == 28) continue;   // handled above

        const float* base = feat
            + (((size_t)img * FH + (size_t)y1) * FW + (size_t)x1) * CCH + coff;
        for (int br = 0; br < PH; ++br) {
            const int rs = (br * roi_h + PH - 1) / PH;
            const int re = (br == PH - 1) ? roi_h
                                          : ((br + 1) * roi_h + PH - 1) / PH;
            for (int bc = 0; bc < PW; ++bc) {
                const int cs = (bc * roi_w + PW - 1) / PW;
                const int ce = (bc == PW - 1) ? roi_w
                                              : ((bc + 1) * roi_w + PW - 1) / PW;
                float2 m = make_float2(-FLT_MAX, -FLT_MAX);
                for (int y = rs; y < re; ++y) {
                    const float* rowp = base + (size_t)y * (FW * CCH);
                    for (int x = cs; x < ce; ++x) {
                        const float2 v =
                            *reinterpret_cast<const float2*>(rowp + (size_t)x * CCH);
                        m = fmax2(m, v);
                    }
                }
                __stwt(reinterpret_cast<float2*>(
                           out + ((size_t)((roi * PH + br) * PW + bc)) * CCH + coff),
                       m);
            }
        }
    }
}

extern "C" void kernel_launch(void* const* d_in, const int* in_sizes, int n_in,
                              void* d_out, int out_size)
{
    const float* feat = (const float*)d_in[0];
    const int*   rois = (const int*)d_in[1];
    const int n_rois = in_sizes[1] / 5;
    float* out = (float*)d_out;

    roi_pool_fused<<<NTILES, 128>>>(feat, rois, out, n_rois);
}